// round 9
// baseline (speedup 1.0000x reference)
#include <cuda_runtime.h>
#include <cuda_fp16.h>

#define FDIM 128
#define F2   16
#define NMAX 100000
#define EMAX 1600000
#define SCAN_TPB 1024
#define NBLK ((NMAX + SCAN_TPB - 1) / SCAN_TPB)   // 98
#define WS_STRIDE 136                              // W smem row stride (conflict-free B frags)

// ---- device scratch (static allocation; no cudaMalloc allowed) ----
__device__ float  g_dinv[NMAX];                  // deg^{-1/2}
__device__ int    g_deg[NMAX];                   // in-degree histogram (per-launch zeroed)
__device__ int    g_rowstart[NMAX + 1];          // CSR row offsets (by dst)
__device__ int    g_cur[NMAX];                   // CSR fill cursors
__device__ int    g_csr[EMAX];                   // CSR column (src) indices
__device__ int    g_bsum[NBLK];                  // per-block degree sums
__device__ __half g_h0[(size_t)NMAX * FDIM];     // (x@W1)*dinv[row], fp16
__device__ float  g_h1[(size_t)NMAX * FDIM];     // relu(aggregated layer 1)
__device__ float  g_t2[(size_t)NMAX * F2];       // (h1@W2) * dinv[row]
__device__ int    g_idx64;                       // 1 if edge_index is int64, 0 if int32

// Flag-dispatched edge read (handles int64 vs int32 edge_index).
__device__ __forceinline__ int edge_at(const void* ei, long long i) {
    if (g_idx64) return (int)((const long long*)ei)[i];
    return ((const int*)ei)[i];
}

__device__ __forceinline__ unsigned f2tf32(float f) {
    unsigned r;
    asm("cvt.rna.tf32.f32 %0, %1;" : "=r"(r) : "f"(f));
    return r;
}

__device__ __forceinline__ void mma_tf32(float* d, unsigned a0, unsigned a1,
                                         unsigned a2, unsigned a3,
                                         unsigned b0, unsigned b1) {
    asm volatile(
        "mma.sync.aligned.m16n8k8.row.col.f32.tf32.tf32.f32 "
        "{%0,%1,%2,%3}, {%4,%5,%6,%7}, {%8,%9}, {%0,%1,%2,%3};"
        : "+f"(d[0]), "+f"(d[1]), "+f"(d[2]), "+f"(d[3])
        : "r"(a0), "r"(a1), "r"(a2), "r"(a3), "r"(b0), "r"(b1));
}

// ---- K1: zero degree histogram; warp 0 of block 0 probes edge dtype. ----
__global__ void zero_probe_k(const unsigned long long* __restrict__ ei, int n) {
    int i = blockIdx.x * blockDim.x + threadIdx.x;
    if (i < n) g_deg[i] = 0;
    if (blockIdx.x == 0 && threadIdx.x < 32) {
        unsigned long long hi = 0;
        #pragma unroll
        for (int j = 0; j < 8; j++) hi |= ei[threadIdx.x + j * 32] >> 32;
        int any = __any_sync(0xffffffffu, hi != 0);
        if (threadIdx.x == 0) g_idx64 = any ? 0 : 1;
    }
}

// ---- K2: in-degree histogram over dst ----
__global__ void hist_k(const void* __restrict__ ei, int e) {
    long long t = (long long)blockIdx.x * blockDim.x + threadIdx.x;
    if (t < e) {
        int d = edge_at(ei, (long long)e + t);
        atomicAdd(&g_deg[d], 1);
    }
}

// Block-wide inclusive scan of one value per thread (1024 threads, 32 warps).
__device__ __forceinline__ int block_scan_1024(int v, int* block_total, int* wsum) {
    int lane = threadIdx.x & 31, w = threadIdx.x >> 5;
    int x = v;
    #pragma unroll
    for (int o = 1; o < 32; o <<= 1) {
        int y = __shfl_up_sync(0xffffffffu, x, o);
        if (lane >= o) x += y;
    }
    if (lane == 31) wsum[w] = x;
    __syncthreads();
    if (w == 0) {
        int s = wsum[lane];
        #pragma unroll
        for (int o = 1; o < 32; o <<= 1) {
            int y = __shfl_up_sync(0xffffffffu, s, o);
            if (lane >= o) s += y;
        }
        wsum[lane] = s;
    }
    __syncthreads();
    int incl = x + (w > 0 ? wsum[w - 1] : 0);
    *block_total = wsum[31];
    return incl;
}

// ---- K3a: per-block degree sums; also computes dinv (so gemm1 can run
//           before the rest of the CSR build). ----
__global__ void scan_phase1_k(int n) {
    __shared__ int wsum[32];
    int i = blockIdx.x * SCAN_TPB + threadIdx.x;
    int v = (i < n) ? g_deg[i] : 0;
    int total;
    block_scan_1024(v, &total, wsum);
    if (threadIdx.x == 0) g_bsum[blockIdx.x] = total;
    if (i < n) g_dinv[i] = rsqrtf((float)(v + 1));   // self-loop adds 1
}

// ---- K3b: local scan; each block computes its own prefix over g_bsum ----
__global__ void scan_phase3_k(int n) {
    __shared__ int wsum[32];
    __shared__ int s_boff;
    if (threadIdx.x < 32) {
        int sum = 0;
        for (int j = threadIdx.x; j < blockIdx.x; j += 32) sum += g_bsum[j];
        #pragma unroll
        for (int o = 16; o > 0; o >>= 1) sum += __shfl_down_sync(0xffffffffu, sum, o);
        if (threadIdx.x == 0) s_boff = sum;
    }
    int i = blockIdx.x * SCAN_TPB + threadIdx.x;
    int v = (i < n) ? g_deg[i] : 0;
    int total;
    int incl = block_scan_1024(v, &total, wsum);
    int boff = s_boff;
    if (i < n) {
        int excl = boff + incl - v;
        g_rowstart[i] = excl;
        g_cur[i] = excl;
    }
    if (blockIdx.x == gridDim.x - 1 && threadIdx.x == 0)
        g_rowstart[n] = boff + total;
}

// ---- K4: fill CSR (src ids bucketed by dst) ----
__global__ void fill_k(const void* __restrict__ ei, int e) {
    long long t = (long long)blockIdx.x * blockDim.x + threadIdx.x;
    if (t < e) {
        int s = edge_at(ei, t);
        int d = edge_at(ei, (long long)e + t);
        int pos = atomicAdd(&g_cur[d], 1);
        g_csr[pos] = s;
    }
}

// ---- K5: g_h0 = (x @ W1) * dinv[row] (fp16 out) via split-TF32 MMA.
// W1's tf32 hi/lo split precomputed ONCE into smem (kills ~1.5K cvt/thread).
// 8 warps/block; block tile = 128 rows; warp tile = 16 rows x 128 cols. ----
__global__ void __launch_bounds__(256) gemm1_k(
        const float* __restrict__ x, const float* __restrict__ W1, int n) {
    extern __shared__ unsigned Wsm[];    // hi [128][WS_STRIDE], lo [128][WS_STRIDE]
    unsigned* Whi = Wsm;
    unsigned* Wlo = Wsm + FDIM * WS_STRIDE;
    int tid = threadIdx.x;
    int warp = tid >> 5, lane = tid & 31;

    #pragma unroll
    for (int i = 0; i < 64; i++) {
        int idx = i * 256 + tid;         // 16384 elements of W1
        int k = idx >> 7, nn = idx & 127;
        float w = W1[idx];
        unsigned hi = f2tf32(w);
        Whi[k * WS_STRIDE + nn] = hi;
        Wlo[k * WS_STRIDE + nn] = f2tf32(w - __uint_as_float(hi));
    }
    __syncthreads();

    int r_base = blockIdx.x * 128 + warp * 16;
    int row_a = r_base + (lane >> 2);    // fragment row (lower 8)
    int quad  = lane & 3;

    float acc[16][4];
    #pragma unroll
    for (int nt = 0; nt < 16; nt++) {
        acc[nt][0] = acc[nt][1] = acc[nt][2] = acc[nt][3] = 0.0f;
    }

    #pragma unroll
    for (int ks = 0; ks < 16; ks++) {
        int k0 = ks * 8;
        float a0f = (row_a < n)     ? __ldg(&x[row_a * FDIM + k0 + quad])           : 0.0f;
        float a1f = (row_a + 8 < n) ? __ldg(&x[(row_a + 8) * FDIM + k0 + quad])     : 0.0f;
        float a2f = (row_a < n)     ? __ldg(&x[row_a * FDIM + k0 + 4 + quad])       : 0.0f;
        float a3f = (row_a + 8 < n) ? __ldg(&x[(row_a + 8) * FDIM + k0 + 4 + quad]) : 0.0f;
        unsigned ah0 = f2tf32(a0f), ah1 = f2tf32(a1f), ah2 = f2tf32(a2f), ah3 = f2tf32(a3f);
        unsigned al0 = f2tf32(a0f - __uint_as_float(ah0));
        unsigned al1 = f2tf32(a1f - __uint_as_float(ah1));
        unsigned al2 = f2tf32(a2f - __uint_as_float(ah2));
        unsigned al3 = f2tf32(a3f - __uint_as_float(ah3));

        int o0 = (k0 + quad) * WS_STRIDE + (lane >> 2);
        int o1 = (k0 + 4 + quad) * WS_STRIDE + (lane >> 2);
        #pragma unroll
        for (int nt = 0; nt < 16; nt++) {
            unsigned bh0 = Whi[o0 + nt * 8];
            unsigned bh1 = Whi[o1 + nt * 8];
            unsigned bl0 = Wlo[o0 + nt * 8];
            unsigned bl1 = Wlo[o1 + nt * 8];
            mma_tf32(acc[nt], ah0, ah1, ah2, ah3, bh0, bh1);
            mma_tf32(acc[nt], al0, al1, al2, al3, bh0, bh1);
            mma_tf32(acc[nt], ah0, ah1, ah2, ah3, bl0, bl1);
        }
    }

    // Epilogue: scale by dinv[row], store fp16 pairs.
    float di0 = (row_a < n)     ? g_dinv[row_a]     : 0.0f;
    float di1 = (row_a + 8 < n) ? g_dinv[row_a + 8] : 0.0f;
    #pragma unroll
    for (int nt = 0; nt < 16; nt++) {
        int col = nt * 8 + quad * 2;
        if (row_a < n) {
            __half2 v = __floats2half2_rn(acc[nt][0] * di0, acc[nt][1] * di0);
            *(__half2*)&g_h0[(size_t)row_a * FDIM + col] = v;
        }
        if (row_a + 8 < n) {
            __half2 v = __floats2half2_rn(acc[nt][2] * di1, acc[nt][3] * di1);
            *(__half2*)&g_h0[(size_t)(row_a + 8) * FDIM + col] = v;
        }
    }
}

// ---- K6: pull-mode layer-1 aggregation + fused finalize.
//          One warp per dst node; lane owns 4 features (8B fp16 load).
//          Neighbor ids batch-loaded coalesced (out of the dep chain);
//          inner loop unrolled by 8 with predication -> 8 gathers in flight. ----
__global__ void pull1_k(const float* __restrict__ b1, int n) {
    int wid_g = (blockIdx.x * blockDim.x + threadIdx.x) >> 5;
    int lane = threadIdx.x & 31;
    if (wid_g >= n) return;
    int beg = g_rowstart[wid_g];
    int end = g_rowstart[wid_g + 1];
    const uint2* H0 = (const uint2*)g_h0;

    uint2 sv = H0[(size_t)wid_g * 32 + lane];            // self-loop term
    float2 s0 = __half22float2(*(const __half2*)&sv.x);
    float2 s1 = __half22float2(*(const __half2*)&sv.y);
    float4 acc = make_float4(s0.x, s0.y, s1.x, s1.y);

    for (int j0 = beg; j0 < end; j0 += 32) {
        int id = (j0 + lane < end) ? g_csr[j0 + lane] : 0;   // one coalesced load
        int m = min(32, end - j0);
        for (int jj = 0; jj < m; jj += 8) {
            #pragma unroll
            for (int k = 0; k < 8; k++) {
                int j = jj + k;
                int s = __shfl_sync(0xffffffffu, id, j & 31);
                if (j < m) {
                    uint2 v = H0[(size_t)s * 32 + lane];
                    float2 p0 = __half22float2(*(const __half2*)&v.x);
                    float2 p1 = __half22float2(*(const __half2*)&v.y);
                    acc.x += p0.x; acc.y += p0.y; acc.z += p1.x; acc.w += p1.y;
                }
            }
        }
    }
    float di = g_dinv[wid_g];
    float4 bb = ((const float4*)b1)[lane];
    acc.x = fmaxf(fmaf(acc.x, di, bb.x), 0.0f);
    acc.y = fmaxf(fmaf(acc.y, di, bb.y), 0.0f);
    acc.z = fmaxf(fmaf(acc.z, di, bb.z), 0.0f);
    acc.w = fmaxf(fmaf(acc.w, di, bb.w), 0.0f);
    ((float4*)g_h1)[(size_t)wid_g * 32 + lane] = acc;
}

// ---- K7: g_t2 = (h1 @ W2) * dinv[row] ----
__global__ void gemm2_k(const float* __restrict__ W2, int n) {
    __shared__ float ws[FDIM * F2];
    __shared__ float hs[8][FDIM];
    int tid = threadIdx.x;               // 128 threads
    #pragma unroll
    for (int i = 0; i < F2; i++) ws[i * FDIM + tid] = W2[i * FDIM + tid];
    long long r0 = (long long)blockIdx.x * 8;
    #pragma unroll
    for (int j = 0; j < 8; j++) {
        long long r = r0 + j;
        hs[j][tid] = (r < n) ? g_h1[r * FDIM + tid] : 0.0f;
    }
    __syncthreads();
    int lr = tid >> 4;                   // local row 0..7
    int c  = tid & 15;                   // col 0..15
    float acc = 0.0f;
    #pragma unroll 8
    for (int k = 0; k < FDIM; k++) acc = fmaf(hs[lr][k], ws[k * F2 + c], acc);
    long long r = r0 + lr;
    if (r < n) g_t2[r * F2 + c] = acc * g_dinv[r];
}

// ---- K8: pull-mode layer-2 aggregation + fused finalize, writes d_out. ----
__global__ void pull2_k(const float* __restrict__ b2, float* __restrict__ out, int n) {
    int t = blockIdx.x * blockDim.x + threadIdx.x;
    if (t >= n * 4) return;
    int node = t >> 2, q = t & 3;
    int beg = g_rowstart[node];
    int end = g_rowstart[node + 1];
    const float4* T2 = (const float4*)g_t2;
    float4 acc = T2[(size_t)node * 4 + q];               // self-loop term
    #pragma unroll 4
    for (int j = beg; j < end; j++) {
        int s = __ldg(&g_csr[j]);
        float4 v = T2[(size_t)s * 4 + q];
        acc.x += v.x; acc.y += v.y; acc.z += v.z; acc.w += v.w;
    }
    float di = g_dinv[node];
    float4 bb = ((const float4*)b2)[q];
    acc.x = fmaf(acc.x, di, bb.x);
    acc.y = fmaf(acc.y, di, bb.y);
    acc.z = fmaf(acc.z, di, bb.z);
    acc.w = fmaf(acc.w, di, bb.w);
    ((float4*)out)[(size_t)node * 4 + q] = acc;
}

extern "C" void kernel_launch(void* const* d_in, const int* in_sizes, int n_in,
                              void* d_out, int out_size) {
    const float* x  = (const float*)d_in[0];
    const void*  ei = d_in[1];
    const float* W1 = (const float*)d_in[2];
    const float* b1 = (const float*)d_in[3];
    const float* W2 = (const float*)d_in[4];
    const float* b2 = (const float*)d_in[5];
    float* out = (float*)d_out;

    int n = in_sizes[0] / FDIM;   // 100000
    int e = in_sizes[1] / 2;      // 1600000

    const int ws_bytes = 2 * FDIM * WS_STRIDE * sizeof(unsigned);  // 139264
    cudaFuncSetAttribute(gemm1_k, cudaFuncAttributeMaxDynamicSharedMemorySize, ws_bytes);

    int nblk = (n + SCAN_TPB - 1) / SCAN_TPB;

    zero_probe_k<<<(n + 255) / 256, 256>>>((const unsigned long long*)ei, n);  // 1
    hist_k<<<(e + 255) / 256, 256>>>(ei, e);                                   // 2
    scan_phase1_k<<<nblk, SCAN_TPB>>>(n);                                      // 3 (also dinv)
    gemm1_k<<<(n + 127) / 128, 256, ws_bytes>>>(x, W1, n);                     // 4 <- ncu capture
    scan_phase3_k<<<nblk, SCAN_TPB>>>(n);                                      // 5
    fill_k<<<(e + 255) / 256, 256>>>(ei, e);                                   // 6

    long long w1t = (long long)n * 32;   // one warp per node
    pull1_k<<<(unsigned)((w1t + 255) / 256), 256>>>(b1, n);                    // 7

    gemm2_k<<<(n + 7) / 8, 128>>>(W2, n);                                      // 8

    long long p2t = (long long)n * 4;    // 4 threads per node
    pull2_k<<<(unsigned)((p2t + 255) / 256), 256>>>(b2, out, n);               // 9
}

// round 10
// speedup vs baseline: 1.2020x; 1.2020x over previous
#include <cuda_runtime.h>
#include <cuda_fp16.h>
#include <cuda_bf16.h>

#define FDIM 128
#define F2   16
#define NMAX 100000
#define EMAX 1600000
#define SCAN_TPB 1024
#define NBLK ((NMAX + SCAN_TPB - 1) / SCAN_TPB)   // 98
#define WP_STRIDE 136                              // packed-W smem row stride (words)

// ---- device scratch (static allocation; no cudaMalloc allowed) ----
__device__ float  g_dinv[NMAX];                  // deg^{-1/2}
__device__ int    g_deg[NMAX];                   // in-degree histogram (per-launch zeroed)
__device__ int    g_rowstart[NMAX + 1];          // CSR row offsets (by dst)
__device__ int    g_cur[NMAX];                   // CSR fill cursors
__device__ int    g_csr[EMAX];                   // CSR column (src) indices
__device__ int    g_bsum[NBLK];                  // per-block degree sums
__device__ __half g_h0[(size_t)NMAX * FDIM];     // (x@W1)*dinv[row], fp16
__device__ float  g_h1[(size_t)NMAX * FDIM];     // relu(aggregated layer 1)
__device__ float  g_t2[(size_t)NMAX * F2];       // (h1@W2) * dinv[row]
__device__ int    g_idx64;                       // 1 if edge_index is int64, 0 if int32

// Flag-dispatched edge read (handles int64 vs int32 edge_index).
__device__ __forceinline__ int edge_at(const void* ei, long long i) {
    if (g_idx64) return (int)((const long long*)ei)[i];
    return ((const int*)ei)[i];
}

// Pack two floats into a bf16x2 word (low = first).
__device__ __forceinline__ unsigned pack_bf2(float a, float b) {
    __nv_bfloat162 h = __floats2bfloat162_rn(a, b);
    return *(unsigned*)&h;
}

__device__ __forceinline__ void mma_bf16(float* d, unsigned a0, unsigned a1,
                                         unsigned a2, unsigned a3,
                                         unsigned b0, unsigned b1) {
    asm volatile(
        "mma.sync.aligned.m16n8k16.row.col.f32.bf16.bf16.f32 "
        "{%0,%1,%2,%3}, {%4,%5,%6,%7}, {%8,%9}, {%0,%1,%2,%3};"
        : "+f"(d[0]), "+f"(d[1]), "+f"(d[2]), "+f"(d[3])
        : "r"(a0), "r"(a1), "r"(a2), "r"(a3), "r"(b0), "r"(b1));
}

// ---- K1: zero degree histogram; warp 0 of block 0 probes edge dtype. ----
__global__ void zero_probe_k(const unsigned long long* __restrict__ ei, int n) {
    int i = blockIdx.x * blockDim.x + threadIdx.x;
    if (i < n) g_deg[i] = 0;
    if (blockIdx.x == 0 && threadIdx.x < 32) {
        unsigned long long hi = 0;
        #pragma unroll
        for (int j = 0; j < 8; j++) hi |= ei[threadIdx.x + j * 32] >> 32;
        int any = __any_sync(0xffffffffu, hi != 0);
        if (threadIdx.x == 0) g_idx64 = any ? 0 : 1;
    }
}

// ---- K2: in-degree histogram over dst ----
__global__ void hist_k(const void* __restrict__ ei, int e) {
    long long t = (long long)blockIdx.x * blockDim.x + threadIdx.x;
    if (t < e) {
        int d = edge_at(ei, (long long)e + t);
        atomicAdd(&g_deg[d], 1);
    }
}

// Block-wide inclusive scan of one value per thread (1024 threads, 32 warps).
__device__ __forceinline__ int block_scan_1024(int v, int* block_total, int* wsum) {
    int lane = threadIdx.x & 31, w = threadIdx.x >> 5;
    int x = v;
    #pragma unroll
    for (int o = 1; o < 32; o <<= 1) {
        int y = __shfl_up_sync(0xffffffffu, x, o);
        if (lane >= o) x += y;
    }
    if (lane == 31) wsum[w] = x;
    __syncthreads();
    if (w == 0) {
        int s = wsum[lane];
        #pragma unroll
        for (int o = 1; o < 32; o <<= 1) {
            int y = __shfl_up_sync(0xffffffffu, s, o);
            if (lane >= o) s += y;
        }
        wsum[lane] = s;
    }
    __syncthreads();
    int incl = x + (w > 0 ? wsum[w - 1] : 0);
    *block_total = wsum[31];
    return incl;
}

// ---- K3a: per-block degree sums; also computes dinv ----
__global__ void scan_phase1_k(int n) {
    __shared__ int wsum[32];
    int i = blockIdx.x * SCAN_TPB + threadIdx.x;
    int v = (i < n) ? g_deg[i] : 0;
    int total;
    block_scan_1024(v, &total, wsum);
    if (threadIdx.x == 0) g_bsum[blockIdx.x] = total;
    if (i < n) g_dinv[i] = rsqrtf((float)(v + 1));   // self-loop adds 1
}

// ---- K3b: local scan; each block computes its own prefix over g_bsum ----
__global__ void scan_phase3_k(int n) {
    __shared__ int wsum[32];
    __shared__ int s_boff;
    if (threadIdx.x < 32) {
        int sum = 0;
        for (int j = threadIdx.x; j < blockIdx.x; j += 32) sum += g_bsum[j];
        #pragma unroll
        for (int o = 16; o > 0; o >>= 1) sum += __shfl_down_sync(0xffffffffu, sum, o);
        if (threadIdx.x == 0) s_boff = sum;
    }
    int i = blockIdx.x * SCAN_TPB + threadIdx.x;
    int v = (i < n) ? g_deg[i] : 0;
    int total;
    int incl = block_scan_1024(v, &total, wsum);
    int boff = s_boff;
    if (i < n) {
        int excl = boff + incl - v;
        g_rowstart[i] = excl;
        g_cur[i] = excl;
    }
    if (blockIdx.x == gridDim.x - 1 && threadIdx.x == 0)
        g_rowstart[n] = boff + total;
}

// ---- K4: fill CSR (src ids bucketed by dst) ----
__global__ void fill_k(const void* __restrict__ ei, int e) {
    long long t = (long long)blockIdx.x * blockDim.x + threadIdx.x;
    if (t < e) {
        int s = edge_at(ei, t);
        int d = edge_at(ei, (long long)e + t);
        int pos = atomicAdd(&g_cur[d], 1);
        g_csr[pos] = s;
    }
}

// ---- K5: g_h0 = (x @ W1) * dinv[row] (fp16 out) via split-bf16 MMA.
// a = bf16(a) + bf16(a - bf16(a)); D = AhBh + AlBh + AhBl (lo*lo ~2^-16 dropped).
// m16n8k16: half the MMAs and half the B-fragment LDS of the tf32 version;
// smem = 69.6KB (hi+lo bf16x2-packed) -> 3 CTAs/SM.
// 8 warps/block; block tile = 128 rows; warp tile = 16 rows x 128 cols. ----
__global__ void __launch_bounds__(256) gemm1_k(
        const float* __restrict__ x, const float* __restrict__ W1, int n) {
    extern __shared__ unsigned Wsm[];    // hi [64][WP_STRIDE], lo [64][WP_STRIDE]
    unsigned* Whi = Wsm;                 // word [kp][n] = bf16x2 (W[2kp][n], W[2kp+1][n])
    unsigned* Wlo = Wsm + 64 * WP_STRIDE;
    int tid = threadIdx.x;
    int warp = tid >> 5, lane = tid & 31;

    // Stage W1 as packed k-pairs: 8192 words, 32 iters of 256 threads.
    #pragma unroll
    for (int i = 0; i < 32; i++) {
        int p = i * 256 + tid;
        int kp = p >> 7, nn = p & 127;
        float w0 = W1[(2 * kp) * FDIM + nn];
        float w1 = W1[(2 * kp + 1) * FDIM + nn];
        unsigned hi = pack_bf2(w0, w1);
        __nv_bfloat162 hb = *(__nv_bfloat162*)&hi;
        Whi[kp * WP_STRIDE + nn] = hi;
        Wlo[kp * WP_STRIDE + nn] = pack_bf2(w0 - __bfloat162float(hb.x),
                                            w1 - __bfloat162float(hb.y));
    }
    __syncthreads();

    int r_base = blockIdx.x * 128 + warp * 16;
    int row_a = r_base + (lane >> 2);    // fragment row (lower 8)
    int tig   = lane & 3;                // thread-in-group
    int colw  = lane >> 2;               // fragment column within 8

    float acc[16][4];
    #pragma unroll
    for (int nt = 0; nt < 16; nt++) {
        acc[nt][0] = acc[nt][1] = acc[nt][2] = acc[nt][3] = 0.0f;
    }

    bool v0 = row_a < n, v1 = row_a + 8 < n;
    const float zero2[2] = {0.0f, 0.0f};

    #pragma unroll
    for (int ks = 0; ks < 8; ks++) {
        int k0 = ks * 16;
        // A fragments: a0=(row,k0+2t..+1) a1=(row+8,..) a2=(row,k0+8+2t..) a3=(row+8,..)
        float2 xa = v0 ? *(const float2*)&x[(size_t)row_a * FDIM + k0 + tig * 2]           : *(const float2*)zero2;
        float2 xb = v0 ? *(const float2*)&x[(size_t)row_a * FDIM + k0 + 8 + tig * 2]       : *(const float2*)zero2;
        float2 xc = v1 ? *(const float2*)&x[(size_t)(row_a + 8) * FDIM + k0 + tig * 2]     : *(const float2*)zero2;
        float2 xd = v1 ? *(const float2*)&x[(size_t)(row_a + 8) * FDIM + k0 + 8 + tig * 2] : *(const float2*)zero2;

        unsigned ah0 = pack_bf2(xa.x, xa.y), ah1 = pack_bf2(xc.x, xc.y);
        unsigned ah2 = pack_bf2(xb.x, xb.y), ah3 = pack_bf2(xd.x, xd.y);
        __nv_bfloat162 h0 = *(__nv_bfloat162*)&ah0, h1 = *(__nv_bfloat162*)&ah1;
        __nv_bfloat162 h2 = *(__nv_bfloat162*)&ah2, h3 = *(__nv_bfloat162*)&ah3;
        unsigned al0 = pack_bf2(xa.x - __bfloat162float(h0.x), xa.y - __bfloat162float(h0.y));
        unsigned al1 = pack_bf2(xc.x - __bfloat162float(h1.x), xc.y - __bfloat162float(h1.y));
        unsigned al2 = pack_bf2(xb.x - __bfloat162float(h2.x), xb.y - __bfloat162float(h2.y));
        unsigned al3 = pack_bf2(xd.x - __bfloat162float(h3.x), xd.y - __bfloat162float(h3.y));

        int o0 = (ks * 8 + tig) * WP_STRIDE + colw;        // k-pair row for k0..k0+7
        int o1 = (ks * 8 + 4 + tig) * WP_STRIDE + colw;    // k-pair row for k0+8..k0+15
        #pragma unroll
        for (int nt = 0; nt < 16; nt++) {
            unsigned bh0 = Whi[o0 + nt * 8];
            unsigned bh1 = Whi[o1 + nt * 8];
            unsigned bl0 = Wlo[o0 + nt * 8];
            unsigned bl1 = Wlo[o1 + nt * 8];
            mma_bf16(acc[nt], ah0, ah1, ah2, ah3, bh0, bh1);
            mma_bf16(acc[nt], al0, al1, al2, al3, bh0, bh1);
            mma_bf16(acc[nt], ah0, ah1, ah2, ah3, bl0, bl1);
        }
    }

    // Epilogue: scale by dinv[row], store fp16 pairs.
    float di0 = v0 ? g_dinv[row_a]     : 0.0f;
    float di1 = v1 ? g_dinv[row_a + 8] : 0.0f;
    #pragma unroll
    for (int nt = 0; nt < 16; nt++) {
        int col = nt * 8 + tig * 2;
        if (v0) {
            __half2 v = __floats2half2_rn(acc[nt][0] * di0, acc[nt][1] * di0);
            *(__half2*)&g_h0[(size_t)row_a * FDIM + col] = v;
        }
        if (v1) {
            __half2 v = __floats2half2_rn(acc[nt][2] * di1, acc[nt][3] * di1);
            *(__half2*)&g_h0[(size_t)(row_a + 8) * FDIM + col] = v;
        }
    }
}

// ---- K6: pull-mode layer-1 aggregation + fused finalize. ----
__global__ void pull1_k(const float* __restrict__ b1, int n) {
    int wid_g = (blockIdx.x * blockDim.x + threadIdx.x) >> 5;
    int lane = threadIdx.x & 31;
    if (wid_g >= n) return;
    int beg = g_rowstart[wid_g];
    int end = g_rowstart[wid_g + 1];
    const uint2* H0 = (const uint2*)g_h0;

    uint2 sv = H0[(size_t)wid_g * 32 + lane];            // self-loop term
    float2 s0 = __half22float2(*(const __half2*)&sv.x);
    float2 s1 = __half22float2(*(const __half2*)&sv.y);
    float4 acc = make_float4(s0.x, s0.y, s1.x, s1.y);

    for (int j0 = beg; j0 < end; j0 += 32) {
        int id = (j0 + lane < end) ? g_csr[j0 + lane] : 0;   // one coalesced load
        int m = min(32, end - j0);
        for (int jj = 0; jj < m; jj += 8) {
            #pragma unroll
            for (int k = 0; k < 8; k++) {
                int j = jj + k;
                int s = __shfl_sync(0xffffffffu, id, j & 31);
                if (j < m) {
                    uint2 v = H0[(size_t)s * 32 + lane];
                    float2 p0 = __half22float2(*(const __half2*)&v.x);
                    float2 p1 = __half22float2(*(const __half2*)&v.y);
                    acc.x += p0.x; acc.y += p0.y; acc.z += p1.x; acc.w += p1.y;
                }
            }
        }
    }
    float di = g_dinv[wid_g];
    float4 bb = ((const float4*)b1)[lane];
    acc.x = fmaxf(fmaf(acc.x, di, bb.x), 0.0f);
    acc.y = fmaxf(fmaf(acc.y, di, bb.y), 0.0f);
    acc.z = fmaxf(fmaf(acc.z, di, bb.z), 0.0f);
    acc.w = fmaxf(fmaf(acc.w, di, bb.w), 0.0f);
    ((float4*)g_h1)[(size_t)wid_g * 32 + lane] = acc;
}

// ---- K7: g_t2 = (h1 @ W2) * dinv[row] ----
__global__ void gemm2_k(const float* __restrict__ W2, int n) {
    __shared__ float ws[FDIM * F2];
    __shared__ float hs[8][FDIM];
    int tid = threadIdx.x;               // 128 threads
    #pragma unroll
    for (int i = 0; i < F2; i++) ws[i * FDIM + tid] = W2[i * FDIM + tid];
    long long r0 = (long long)blockIdx.x * 8;
    #pragma unroll
    for (int j = 0; j < 8; j++) {
        long long r = r0 + j;
        hs[j][tid] = (r < n) ? g_h1[r * FDIM + tid] : 0.0f;
    }
    __syncthreads();
    int lr = tid >> 4;                   // local row 0..7
    int c  = tid & 15;                   // col 0..15
    float acc = 0.0f;
    #pragma unroll 8
    for (int k = 0; k < FDIM; k++) acc = fmaf(hs[lr][k], ws[k * F2 + c], acc);
    long long r = r0 + lr;
    if (r < n) g_t2[r * F2 + c] = acc * g_dinv[r];
}

// ---- K8: pull-mode layer-2 aggregation + fused finalize, writes d_out. ----
__global__ void pull2_k(const float* __restrict__ b2, float* __restrict__ out, int n) {
    int t = blockIdx.x * blockDim.x + threadIdx.x;
    if (t >= n * 4) return;
    int node = t >> 2, q = t & 3;
    int beg = g_rowstart[node];
    int end = g_rowstart[node + 1];
    const float4* T2 = (const float4*)g_t2;
    float4 acc = T2[(size_t)node * 4 + q];               // self-loop term
    #pragma unroll 4
    for (int j = beg; j < end; j++) {
        int s = __ldg(&g_csr[j]);
        float4 v = T2[(size_t)s * 4 + q];
        acc.x += v.x; acc.y += v.y; acc.z += v.z; acc.w += v.w;
    }
    float di = g_dinv[node];
    float4 bb = ((const float4*)b2)[q];
    acc.x = fmaf(acc.x, di, bb.x);
    acc.y = fmaf(acc.y, di, bb.y);
    acc.z = fmaf(acc.z, di, bb.z);
    acc.w = fmaf(acc.w, di, bb.w);
    ((float4*)out)[(size_t)node * 4 + q] = acc;
}

extern "C" void kernel_launch(void* const* d_in, const int* in_sizes, int n_in,
                              void* d_out, int out_size) {
    const float* x  = (const float*)d_in[0];
    const void*  ei = d_in[1];
    const float* W1 = (const float*)d_in[2];
    const float* b1 = (const float*)d_in[3];
    const float* W2 = (const float*)d_in[4];
    const float* b2 = (const float*)d_in[5];
    float* out = (float*)d_out;

    int n = in_sizes[0] / FDIM;   // 100000
    int e = in_sizes[1] / 2;      // 1600000

    const int ws_bytes = 2 * 64 * WP_STRIDE * sizeof(unsigned);  // 69632
    cudaFuncSetAttribute(gemm1_k, cudaFuncAttributeMaxDynamicSharedMemorySize, ws_bytes);

    int nblk = (n + SCAN_TPB - 1) / SCAN_TPB;

    zero_probe_k<<<(n + 255) / 256, 256>>>((const unsigned long long*)ei, n);  // 1
    hist_k<<<(e + 255) / 256, 256>>>(ei, e);                                   // 2
    scan_phase1_k<<<nblk, SCAN_TPB>>>(n);                                      // 3 (also dinv)
    gemm1_k<<<(n + 127) / 128, 256, ws_bytes>>>(x, W1, n);                     // 4 <- ncu capture
    scan_phase3_k<<<nblk, SCAN_TPB>>>(n);                                      // 5
    fill_k<<<(e + 255) / 256, 256>>>(ei, e);                                   // 6

    long long w1t = (long long)n * 32;   // one warp per node
    pull1_k<<<(unsigned)((w1t + 255) / 256), 256>>>(b1, n);                    // 7

    gemm2_k<<<(n + 7) / 8, 128>>>(W2, n);                                      // 8

    long long p2t = (long long)n * 4;    // 4 threads per node
    pull2_k<<<(unsigned)((p2t + 255) / 256), 256>>>(b2, out, n);               // 9
}

// round 11
// speedup vs baseline: 1.2143x; 1.0103x over previous
#include <cuda_runtime.h>
#include <cuda_fp16.h>
#include <cuda_bf16.h>

#define FDIM 128
#define F2   16
#define NMAX 100000
#define EMAX 1600000
#define SCAN_TPB 1024
#define NBLK ((NMAX + SCAN_TPB - 1) / SCAN_TPB)   // 98
#define WP_STRIDE 136                              // packed-W smem row stride (words)

// ---- device scratch (static allocation; no cudaMalloc allowed) ----
__device__ float  g_dinv[NMAX];                  // deg^{-1/2}
__device__ int    g_deg[NMAX];                   // in-degree histogram (per-launch zeroed)
__device__ int    g_rowstart[NMAX + 1];          // CSR row offsets (by dst)
__device__ int    g_cur[NMAX];                   // CSR fill cursors
__device__ int    g_csr[EMAX];                   // CSR column (src) indices
__device__ int    g_bsum[NBLK];                  // per-block degree sums
__device__ __half g_h0[(size_t)NMAX * FDIM];     // (x@W1)*dinv[row], fp16
__device__ float  g_h1[(size_t)NMAX * FDIM];     // relu(aggregated layer 1)
__device__ __half g_t2[(size_t)NMAX * F2];       // (h1@W2)*dinv[row], fp16
__device__ int    g_idx64;                       // 1 if edge_index is int64, 0 if int32

// Flag-dispatched edge read (handles int64 vs int32 edge_index).
__device__ __forceinline__ int edge_at(const void* ei, long long i) {
    if (g_idx64) return (int)((const long long*)ei)[i];
    return ((const int*)ei)[i];
}

// Pack two floats into a bf16x2 word (low = first).
__device__ __forceinline__ unsigned pack_bf2(float a, float b) {
    __nv_bfloat162 h = __floats2bfloat162_rn(a, b);
    return *(unsigned*)&h;
}

__device__ __forceinline__ void mma_bf16(float* d, unsigned a0, unsigned a1,
                                         unsigned a2, unsigned a3,
                                         unsigned b0, unsigned b1) {
    asm volatile(
        "mma.sync.aligned.m16n8k16.row.col.f32.bf16.bf16.f32 "
        "{%0,%1,%2,%3}, {%4,%5,%6,%7}, {%8,%9}, {%0,%1,%2,%3};"
        : "+f"(d[0]), "+f"(d[1]), "+f"(d[2]), "+f"(d[3])
        : "r"(a0), "r"(a1), "r"(a2), "r"(a3), "r"(b0), "r"(b1));
}

// ---- K1: zero degree histogram; warp 0 of block 0 probes edge dtype. ----
__global__ void zero_probe_k(const unsigned long long* __restrict__ ei, int n) {
    int i = blockIdx.x * blockDim.x + threadIdx.x;
    if (i < n) g_deg[i] = 0;
    if (blockIdx.x == 0 && threadIdx.x < 32) {
        unsigned long long hi = 0;
        #pragma unroll
        for (int j = 0; j < 8; j++) hi |= ei[threadIdx.x + j * 32] >> 32;
        int any = __any_sync(0xffffffffu, hi != 0);
        if (threadIdx.x == 0) g_idx64 = any ? 0 : 1;
    }
}

// ---- K2: in-degree histogram over dst ----
__global__ void hist_k(const void* __restrict__ ei, int e) {
    long long t = (long long)blockIdx.x * blockDim.x + threadIdx.x;
    if (t < e) {
        int d = edge_at(ei, (long long)e + t);
        atomicAdd(&g_deg[d], 1);
    }
}

// Block-wide inclusive scan of one value per thread (1024 threads, 32 warps).
__device__ __forceinline__ int block_scan_1024(int v, int* block_total, int* wsum) {
    int lane = threadIdx.x & 31, w = threadIdx.x >> 5;
    int x = v;
    #pragma unroll
    for (int o = 1; o < 32; o <<= 1) {
        int y = __shfl_up_sync(0xffffffffu, x, o);
        if (lane >= o) x += y;
    }
    if (lane == 31) wsum[w] = x;
    __syncthreads();
    if (w == 0) {
        int s = wsum[lane];
        #pragma unroll
        for (int o = 1; o < 32; o <<= 1) {
            int y = __shfl_up_sync(0xffffffffu, s, o);
            if (lane >= o) s += y;
        }
        wsum[lane] = s;
    }
    __syncthreads();
    int incl = x + (w > 0 ? wsum[w - 1] : 0);
    *block_total = wsum[31];
    return incl;
}

// ---- K3a: per-block degree sums; also computes dinv ----
__global__ void scan_phase1_k(int n) {
    __shared__ int wsum[32];
    int i = blockIdx.x * SCAN_TPB + threadIdx.x;
    int v = (i < n) ? g_deg[i] : 0;
    int total;
    block_scan_1024(v, &total, wsum);
    if (threadIdx.x == 0) g_bsum[blockIdx.x] = total;
    if (i < n) g_dinv[i] = rsqrtf((float)(v + 1));   // self-loop adds 1
}

// ---- K3b: local scan; each block computes its own prefix over g_bsum ----
__global__ void scan_phase3_k(int n) {
    __shared__ int wsum[32];
    __shared__ int s_boff;
    if (threadIdx.x < 32) {
        int sum = 0;
        for (int j = threadIdx.x; j < blockIdx.x; j += 32) sum += g_bsum[j];
        #pragma unroll
        for (int o = 16; o > 0; o >>= 1) sum += __shfl_down_sync(0xffffffffu, sum, o);
        if (threadIdx.x == 0) s_boff = sum;
    }
    int i = blockIdx.x * SCAN_TPB + threadIdx.x;
    int v = (i < n) ? g_deg[i] : 0;
    int total;
    int incl = block_scan_1024(v, &total, wsum);
    int boff = s_boff;
    if (i < n) {
        int excl = boff + incl - v;
        g_rowstart[i] = excl;
        g_cur[i] = excl;
    }
    if (blockIdx.x == gridDim.x - 1 && threadIdx.x == 0)
        g_rowstart[n] = boff + total;
}

// ---- K4: fill CSR (src ids bucketed by dst) ----
__global__ void fill_k(const void* __restrict__ ei, int e) {
    long long t = (long long)blockIdx.x * blockDim.x + threadIdx.x;
    if (t < e) {
        int s = edge_at(ei, t);
        int d = edge_at(ei, (long long)e + t);
        int pos = atomicAdd(&g_cur[d], 1);
        g_csr[pos] = s;
    }
}

// ---- K5: g_h0 = (x @ W1) * dinv[row] (fp16 out) via split-bf16 MMA.
// 32 rows per warp (two m16 A-tiles) share every B fragment -> B-LDS per MMA
// halves vs R9. 128-thread blocks, block tile = 128 rows.
// launch_bounds(128,3): 3 CTAs/SM by regs (~170 cap) and smem (69.6KB). ----
__global__ void __launch_bounds__(128, 3) gemm1_k(
        const float* __restrict__ x, const float* __restrict__ W1, int n) {
    extern __shared__ unsigned Wsm[];    // hi [64][WP_STRIDE], lo [64][WP_STRIDE]
    unsigned* Whi = Wsm;                 // word [kp][n] = bf16x2 (W[2kp][n], W[2kp+1][n])
    unsigned* Wlo = Wsm + 64 * WP_STRIDE;
    int tid = threadIdx.x;
    int warp = tid >> 5, lane = tid & 31;

    // Stage W1 as packed k-pairs: 8192 words, 64 iters of 128 threads.
    #pragma unroll
    for (int i = 0; i < 64; i++) {
        int p = i * 128 + tid;
        int kp = p >> 7, nn = p & 127;
        float w0 = W1[(2 * kp) * FDIM + nn];
        float w1 = W1[(2 * kp + 1) * FDIM + nn];
        unsigned hi = pack_bf2(w0, w1);
        __nv_bfloat162 hb = *(__nv_bfloat162*)&hi;
        Whi[kp * WP_STRIDE + nn] = hi;
        Wlo[kp * WP_STRIDE + nn] = pack_bf2(w0 - __bfloat162float(hb.x),
                                            w1 - __bfloat162float(hb.y));
    }
    __syncthreads();

    int r_base = blockIdx.x * 128 + warp * 32;
    int row_a = r_base + (lane >> 2);    // tile0 lower row; tile1 = +16
    int tig   = lane & 3;                // thread-in-group
    int colw  = lane >> 2;               // fragment column within 8

    float acc[2][16][4];
    #pragma unroll
    for (int tt = 0; tt < 2; tt++)
        #pragma unroll
        for (int nt = 0; nt < 16; nt++) {
            acc[tt][nt][0] = acc[tt][nt][1] = acc[tt][nt][2] = acc[tt][nt][3] = 0.0f;
        }

    bool v0 = row_a < n, v1 = row_a + 8 < n, v2 = row_a + 16 < n, v3 = row_a + 24 < n;
    const float zero2[2] = {0.0f, 0.0f};

    #pragma unroll
    for (int ks = 0; ks < 8; ks++) {
        int k0 = ks * 16;
        unsigned AH[2][4], AL[2][4];
        #pragma unroll
        for (int tt = 0; tt < 2; tt++) {
            int r = row_a + tt * 16;
            bool p0 = tt ? v2 : v0, p1 = tt ? v3 : v1;
            float2 xa = p0 ? *(const float2*)&x[(size_t)r * FDIM + k0 + tig * 2]            : *(const float2*)zero2;
            float2 xb = p0 ? *(const float2*)&x[(size_t)r * FDIM + k0 + 8 + tig * 2]        : *(const float2*)zero2;
            float2 xc = p1 ? *(const float2*)&x[(size_t)(r + 8) * FDIM + k0 + tig * 2]      : *(const float2*)zero2;
            float2 xd = p1 ? *(const float2*)&x[(size_t)(r + 8) * FDIM + k0 + 8 + tig * 2]  : *(const float2*)zero2;
            unsigned h0 = pack_bf2(xa.x, xa.y), h1 = pack_bf2(xc.x, xc.y);
            unsigned h2 = pack_bf2(xb.x, xb.y), h3 = pack_bf2(xd.x, xd.y);
            __nv_bfloat162 b0 = *(__nv_bfloat162*)&h0, b1 = *(__nv_bfloat162*)&h1;
            __nv_bfloat162 b2 = *(__nv_bfloat162*)&h2, b3 = *(__nv_bfloat162*)&h3;
            AH[tt][0] = h0; AH[tt][1] = h1; AH[tt][2] = h2; AH[tt][3] = h3;
            AL[tt][0] = pack_bf2(xa.x - __bfloat162float(b0.x), xa.y - __bfloat162float(b0.y));
            AL[tt][1] = pack_bf2(xc.x - __bfloat162float(b1.x), xc.y - __bfloat162float(b1.y));
            AL[tt][2] = pack_bf2(xb.x - __bfloat162float(b2.x), xb.y - __bfloat162float(b2.y));
            AL[tt][3] = pack_bf2(xd.x - __bfloat162float(b3.x), xd.y - __bfloat162float(b3.y));
        }

        int o0 = (ks * 8 + tig) * WP_STRIDE + colw;        // k-pairs k0..k0+7
        int o1 = (ks * 8 + 4 + tig) * WP_STRIDE + colw;    // k-pairs k0+8..k0+15
        #pragma unroll
        for (int nt = 0; nt < 16; nt++) {
            unsigned bh0 = Whi[o0 + nt * 8];
            unsigned bh1 = Whi[o1 + nt * 8];
            unsigned bl0 = Wlo[o0 + nt * 8];
            unsigned bl1 = Wlo[o1 + nt * 8];
            #pragma unroll
            for (int tt = 0; tt < 2; tt++) {
                mma_bf16(acc[tt][nt], AH[tt][0], AH[tt][1], AH[tt][2], AH[tt][3], bh0, bh1);
                mma_bf16(acc[tt][nt], AL[tt][0], AL[tt][1], AL[tt][2], AL[tt][3], bh0, bh1);
                mma_bf16(acc[tt][nt], AH[tt][0], AH[tt][1], AH[tt][2], AH[tt][3], bl0, bl1);
            }
        }
    }

    // Epilogue: scale by dinv[row], store fp16 pairs.
    #pragma unroll
    for (int tt = 0; tt < 2; tt++) {
        int r0 = row_a + tt * 16;
        bool p0 = tt ? v2 : v0, p1 = tt ? v3 : v1;
        float di0 = p0 ? g_dinv[r0]     : 0.0f;
        float di1 = p1 ? g_dinv[r0 + 8] : 0.0f;
        #pragma unroll
        for (int nt = 0; nt < 16; nt++) {
            int col = nt * 8 + tig * 2;
            if (p0) {
                __half2 v = __floats2half2_rn(acc[tt][nt][0] * di0, acc[tt][nt][1] * di0);
                *(__half2*)&g_h0[(size_t)r0 * FDIM + col] = v;
            }
            if (p1) {
                __half2 v = __floats2half2_rn(acc[tt][nt][2] * di1, acc[tt][nt][3] * di1);
                *(__half2*)&g_h0[(size_t)(r0 + 8) * FDIM + col] = v;
            }
        }
    }
}

// ---- K6: pull-mode layer-1 aggregation + fused finalize. ----
__global__ void pull1_k(const float* __restrict__ b1, int n) {
    int wid_g = (blockIdx.x * blockDim.x + threadIdx.x) >> 5;
    int lane = threadIdx.x & 31;
    if (wid_g >= n) return;
    int beg = g_rowstart[wid_g];
    int end = g_rowstart[wid_g + 1];
    const uint2* H0 = (const uint2*)g_h0;

    uint2 sv = H0[(size_t)wid_g * 32 + lane];            // self-loop term
    float2 s0 = __half22float2(*(const __half2*)&sv.x);
    float2 s1 = __half22float2(*(const __half2*)&sv.y);
    float4 acc = make_float4(s0.x, s0.y, s1.x, s1.y);

    for (int j0 = beg; j0 < end; j0 += 32) {
        int id = (j0 + lane < end) ? g_csr[j0 + lane] : 0;   // one coalesced load
        int m = min(32, end - j0);
        for (int jj = 0; jj < m; jj += 8) {
            #pragma unroll
            for (int k = 0; k < 8; k++) {
                int j = jj + k;
                int s = __shfl_sync(0xffffffffu, id, j & 31);
                if (j < m) {
                    uint2 v = H0[(size_t)s * 32 + lane];
                    float2 p0 = __half22float2(*(const __half2*)&v.x);
                    float2 p1 = __half22float2(*(const __half2*)&v.y);
                    acc.x += p0.x; acc.y += p0.y; acc.z += p1.x; acc.w += p1.y;
                }
            }
        }
    }
    float di = g_dinv[wid_g];
    float4 bb = ((const float4*)b1)[lane];
    acc.x = fmaxf(fmaf(acc.x, di, bb.x), 0.0f);
    acc.y = fmaxf(fmaf(acc.y, di, bb.y), 0.0f);
    acc.z = fmaxf(fmaf(acc.z, di, bb.z), 0.0f);
    acc.w = fmaxf(fmaf(acc.w, di, bb.w), 0.0f);
    ((float4*)g_h1)[(size_t)wid_g * 32 + lane] = acc;
}

// ---- K7: g_t2 = (h1 @ W2) * dinv[row], fp16 out ----
__global__ void gemm2_k(const float* __restrict__ W2, int n) {
    __shared__ float ws[FDIM * F2];
    __shared__ float hs[8][FDIM];
    int tid = threadIdx.x;               // 128 threads
    #pragma unroll
    for (int i = 0; i < F2; i++) ws[i * FDIM + tid] = W2[i * FDIM + tid];
    long long r0 = (long long)blockIdx.x * 8;
    #pragma unroll
    for (int j = 0; j < 8; j++) {
        long long r = r0 + j;
        hs[j][tid] = (r < n) ? g_h1[r * FDIM + tid] : 0.0f;
    }
    __syncthreads();
    int lr = tid >> 4;                   // local row 0..7
    int c  = tid & 15;                   // col 0..15
    float acc = 0.0f;
    #pragma unroll 8
    for (int k = 0; k < FDIM; k++) acc = fmaf(hs[lr][k], ws[k * F2 + c], acc);
    long long r = r0 + lr;
    if (r < n) g_t2[r * F2 + c] = __float2half_rn(acc * g_dinv[r]);
}

// ---- K8: pull-mode layer-2 aggregation + fused finalize, writes d_out.
//          4 threads/node; each owns 4 features (one 8B fp16 load/edge). ----
__global__ void pull2_k(const float* __restrict__ b2, float* __restrict__ out, int n) {
    int t = blockIdx.x * blockDim.x + threadIdx.x;
    if (t >= n * 4) return;
    int node = t >> 2, q = t & 3;
    int beg = g_rowstart[node];
    int end = g_rowstart[node + 1];
    const uint2* T2 = (const uint2*)g_t2;

    uint2 sv = T2[(size_t)node * 4 + q];                 // self-loop term
    float2 s0 = __half22float2(*(const __half2*)&sv.x);
    float2 s1 = __half22float2(*(const __half2*)&sv.y);
    float4 acc = make_float4(s0.x, s0.y, s1.x, s1.y);

    #pragma unroll 4
    for (int j = beg; j < end; j++) {
        int s = __ldg(&g_csr[j]);
        uint2 v = T2[(size_t)s * 4 + q];
        float2 p0 = __half22float2(*(const __half2*)&v.x);
        float2 p1 = __half22float2(*(const __half2*)&v.y);
        acc.x += p0.x; acc.y += p0.y; acc.z += p1.x; acc.w += p1.y;
    }
    float di = g_dinv[node];
    float4 bb = ((const float4*)b2)[q];
    acc.x = fmaf(acc.x, di, bb.x);
    acc.y = fmaf(acc.y, di, bb.y);
    acc.z = fmaf(acc.z, di, bb.z);
    acc.w = fmaf(acc.w, di, bb.w);
    ((float4*)out)[(size_t)node * 4 + q] = acc;
}

extern "C" void kernel_launch(void* const* d_in, const int* in_sizes, int n_in,
                              void* d_out, int out_size) {
    const float* x  = (const float*)d_in[0];
    const void*  ei = d_in[1];
    const float* W1 = (const float*)d_in[2];
    const float* b1 = (const float*)d_in[3];
    const float* W2 = (const float*)d_in[4];
    const float* b2 = (const float*)d_in[5];
    float* out = (float*)d_out;

    int n = in_sizes[0] / FDIM;   // 100000
    int e = in_sizes[1] / 2;      // 1600000

    const int ws_bytes = 2 * 64 * WP_STRIDE * sizeof(unsigned);  // 69632
    cudaFuncSetAttribute(gemm1_k, cudaFuncAttributeMaxDynamicSharedMemorySize, ws_bytes);

    int nblk = (n + SCAN_TPB - 1) / SCAN_TPB;

    zero_probe_k<<<(n + 255) / 256, 256>>>((const unsigned long long*)ei, n);  // 1
    hist_k<<<(e + 255) / 256, 256>>>(ei, e);                                   // 2
    scan_phase1_k<<<nblk, SCAN_TPB>>>(n);                                      // 3 (also dinv)
    gemm1_k<<<(n + 127) / 128, 128, ws_bytes>>>(x, W1, n);                     // 4 <- ncu capture
    scan_phase3_k<<<nblk, SCAN_TPB>>>(n);                                      // 5
    fill_k<<<(e + 255) / 256, 256>>>(ei, e);                                   // 6

    long long w1t = (long long)n * 32;   // one warp per node
    pull1_k<<<(unsigned)((w1t + 255) / 256), 256>>>(b1, n);                    // 7

    gemm2_k<<<(n + 7) / 8, 128>>>(W2, n);                                      // 8

    long long p2t = (long long)n * 4;    // 4 threads per node
    pull2_k<<<(unsigned)((p2t + 255) / 256), 256>>>(b2, out, n);               // 9
}

// round 12
// speedup vs baseline: 1.2394x; 1.0206x over previous
#include <cuda_runtime.h>
#include <cuda_fp16.h>

#define FDIM 128
#define F2   16
#define NMAX 100000
#define EMAX 1600000
#define SCAN_TPB 1024
#define NBLK ((NMAX + SCAN_TPB - 1) / SCAN_TPB)   // 98
#define WP_STRIDE 136                              // packed-W smem row stride (words)

// ---- device scratch (static allocation; no cudaMalloc allowed) ----
__device__ float  g_dinv[NMAX];                  // deg^{-1/2}
__device__ int    g_deg[NMAX];                   // in-degree histogram (per-launch zeroed)
__device__ int    g_rowstart[NMAX + 1];          // CSR row offsets (by dst)
__device__ int    g_cur[NMAX];                   // CSR fill cursors
__device__ int    g_csr[EMAX];                   // CSR column (src) indices
__device__ int    g_bsum[NBLK];                  // per-block degree sums
__device__ __half g_h0[(size_t)NMAX * FDIM];     // (x@W1)*dinv[row], fp16
__device__ float  g_h1[(size_t)NMAX * FDIM];     // relu(aggregated layer 1)
__device__ __half g_t2[(size_t)NMAX * F2];       // (h1@W2)*dinv[row], fp16
__device__ int    g_idx64;                       // 1 if edge_index is int64, 0 if int32

// Flag-dispatched edge read (handles int64 vs int32 edge_index).
__device__ __forceinline__ int edge_at(const void* ei, long long i) {
    if (g_idx64) return (int)((const long long*)ei)[i];
    return ((const int*)ei)[i];
}

// Pack two floats into an fp16x2 word (low = first).
__device__ __forceinline__ unsigned pack_h2(float a, float b) {
    __half2 h = __floats2half2_rn(a, b);
    return *(unsigned*)&h;
}

__device__ __forceinline__ void mma_f16(float* d, unsigned a0, unsigned a1,
                                        unsigned a2, unsigned a3,
                                        unsigned b0, unsigned b1) {
    asm volatile(
        "mma.sync.aligned.m16n8k16.row.col.f32.f16.f16.f32 "
        "{%0,%1,%2,%3}, {%4,%5,%6,%7}, {%8,%9}, {%0,%1,%2,%3};"
        : "+f"(d[0]), "+f"(d[1]), "+f"(d[2]), "+f"(d[3])
        : "r"(a0), "r"(a1), "r"(a2), "r"(a3), "r"(b0), "r"(b1));
}

// ---- K1: zero degree histogram; warp 0 of block 0 probes edge dtype. ----
__global__ void zero_probe_k(const unsigned long long* __restrict__ ei, int n) {
    int i = blockIdx.x * blockDim.x + threadIdx.x;
    if (i < n) g_deg[i] = 0;
    if (blockIdx.x == 0 && threadIdx.x < 32) {
        unsigned long long hi = 0;
        #pragma unroll
        for (int j = 0; j < 8; j++) hi |= ei[threadIdx.x + j * 32] >> 32;
        int any = __any_sync(0xffffffffu, hi != 0);
        if (threadIdx.x == 0) g_idx64 = any ? 0 : 1;
    }
}

// ---- K2: in-degree histogram over dst ----
__global__ void hist_k(const void* __restrict__ ei, int e) {
    long long t = (long long)blockIdx.x * blockDim.x + threadIdx.x;
    if (t < e) {
        int d = edge_at(ei, (long long)e + t);
        atomicAdd(&g_deg[d], 1);
    }
}

// Block-wide inclusive scan of one value per thread (1024 threads, 32 warps).
__device__ __forceinline__ int block_scan_1024(int v, int* block_total, int* wsum) {
    int lane = threadIdx.x & 31, w = threadIdx.x >> 5;
    int x = v;
    #pragma unroll
    for (int o = 1; o < 32; o <<= 1) {
        int y = __shfl_up_sync(0xffffffffu, x, o);
        if (lane >= o) x += y;
    }
    if (lane == 31) wsum[w] = x;
    __syncthreads();
    if (w == 0) {
        int s = wsum[lane];
        #pragma unroll
        for (int o = 1; o < 32; o <<= 1) {
            int y = __shfl_up_sync(0xffffffffu, s, o);
            if (lane >= o) s += y;
        }
        wsum[lane] = s;
    }
    __syncthreads();
    int incl = x + (w > 0 ? wsum[w - 1] : 0);
    *block_total = wsum[31];
    return incl;
}

// ---- K3a: per-block degree sums; also computes dinv ----
__global__ void scan_phase1_k(int n) {
    __shared__ int wsum[32];
    int i = blockIdx.x * SCAN_TPB + threadIdx.x;
    int v = (i < n) ? g_deg[i] : 0;
    int total;
    block_scan_1024(v, &total, wsum);
    if (threadIdx.x == 0) g_bsum[blockIdx.x] = total;
    if (i < n) g_dinv[i] = rsqrtf((float)(v + 1));   // self-loop adds 1
}

// ---- K3b: local scan; each block computes its own prefix over g_bsum ----
__global__ void scan_phase3_k(int n) {
    __shared__ int wsum[32];
    __shared__ int s_boff;
    if (threadIdx.x < 32) {
        int sum = 0;
        for (int j = threadIdx.x; j < blockIdx.x; j += 32) sum += g_bsum[j];
        #pragma unroll
        for (int o = 16; o > 0; o >>= 1) sum += __shfl_down_sync(0xffffffffu, sum, o);
        if (threadIdx.x == 0) s_boff = sum;
    }
    int i = blockIdx.x * SCAN_TPB + threadIdx.x;
    int v = (i < n) ? g_deg[i] : 0;
    int total;
    int incl = block_scan_1024(v, &total, wsum);
    int boff = s_boff;
    if (i < n) {
        int excl = boff + incl - v;
        g_rowstart[i] = excl;
        g_cur[i] = excl;
    }
    if (blockIdx.x == gridDim.x - 1 && threadIdx.x == 0)
        g_rowstart[n] = boff + total;
}

// ---- K4: fill CSR (src ids bucketed by dst) ----
__global__ void fill_k(const void* __restrict__ ei, int e) {
    long long t = (long long)blockIdx.x * blockDim.x + threadIdx.x;
    if (t < e) {
        int s = edge_at(ei, t);
        int d = edge_at(ei, (long long)e + t);
        int pos = atomicAdd(&g_cur[d], 1);
        g_csr[pos] = s;
    }
}

// ---- K5: g_h0 = (x @ W1) * dinv[row] (fp16 out) via 2-term fp16-split MMA.
// A = Ah + Al (exact to 2^-21); B truncated to fp16 in smem (single array).
// D = Ah*Bh + Al*Bh = A*Bh; B-rounding adds ~2.4e-4 relative on h0.
// 8 warps/block of 256 thr; warp tile 16x128; block tile 128 rows.
// smem 34.8KB + acc 64 regs -> launch_bounds(256,3) for ~50% occupancy. ----
__global__ void __launch_bounds__(256, 3) gemm1_k(
        const float* __restrict__ x, const float* __restrict__ W1, int n) {
    extern __shared__ unsigned Wsm[];    // [64][WP_STRIDE]: word [kp][n] = fp16x2
    int tid = threadIdx.x;
    int warp = tid >> 5, lane = tid & 31;

    // Stage W1 as packed fp16 k-pairs: 8192 words, 32 iters of 256 threads.
    #pragma unroll
    for (int i = 0; i < 32; i++) {
        int p = i * 256 + tid;
        int kp = p >> 7, nn = p & 127;
        Wsm[kp * WP_STRIDE + nn] = pack_h2(W1[(2 * kp) * FDIM + nn],
                                           W1[(2 * kp + 1) * FDIM + nn]);
    }
    __syncthreads();

    int r_base = blockIdx.x * 128 + warp * 16;
    int row_a = r_base + (lane >> 2);    // fragment row (lower 8)
    int tig   = lane & 3;                // thread-in-group
    int colw  = lane >> 2;               // fragment column within 8

    float acc[16][4];
    #pragma unroll
    for (int nt = 0; nt < 16; nt++) {
        acc[nt][0] = acc[nt][1] = acc[nt][2] = acc[nt][3] = 0.0f;
    }

    bool v0 = row_a < n, v1 = row_a + 8 < n;
    const float zero2[2] = {0.0f, 0.0f};

    #pragma unroll
    for (int ks = 0; ks < 8; ks++) {
        int k0 = ks * 16;
        float2 xa = v0 ? *(const float2*)&x[(size_t)row_a * FDIM + k0 + tig * 2]           : *(const float2*)zero2;
        float2 xb = v0 ? *(const float2*)&x[(size_t)row_a * FDIM + k0 + 8 + tig * 2]       : *(const float2*)zero2;
        float2 xc = v1 ? *(const float2*)&x[(size_t)(row_a + 8) * FDIM + k0 + tig * 2]     : *(const float2*)zero2;
        float2 xd = v1 ? *(const float2*)&x[(size_t)(row_a + 8) * FDIM + k0 + 8 + tig * 2] : *(const float2*)zero2;

        unsigned ah0 = pack_h2(xa.x, xa.y), ah1 = pack_h2(xc.x, xc.y);
        unsigned ah2 = pack_h2(xb.x, xb.y), ah3 = pack_h2(xd.x, xd.y);
        __half2 h0 = *(__half2*)&ah0, h1 = *(__half2*)&ah1;
        __half2 h2 = *(__half2*)&ah2, h3 = *(__half2*)&ah3;
        unsigned al0 = pack_h2(xa.x - __half2float(h0.x), xa.y - __half2float(h0.y));
        unsigned al1 = pack_h2(xc.x - __half2float(h1.x), xc.y - __half2float(h1.y));
        unsigned al2 = pack_h2(xb.x - __half2float(h2.x), xb.y - __half2float(h2.y));
        unsigned al3 = pack_h2(xd.x - __half2float(h3.x), xd.y - __half2float(h3.y));

        int o0 = (ks * 8 + tig) * WP_STRIDE + colw;        // k-pairs k0..k0+7
        int o1 = (ks * 8 + 4 + tig) * WP_STRIDE + colw;    // k-pairs k0+8..k0+15
        #pragma unroll
        for (int nt = 0; nt < 16; nt++) {
            unsigned bh0 = Wsm[o0 + nt * 8];
            unsigned bh1 = Wsm[o1 + nt * 8];
            mma_f16(acc[nt], ah0, ah1, ah2, ah3, bh0, bh1);
            mma_f16(acc[nt], al0, al1, al2, al3, bh0, bh1);
        }
    }

    // Epilogue: scale by dinv[row], store fp16 pairs.
    float di0 = v0 ? g_dinv[row_a]     : 0.0f;
    float di1 = v1 ? g_dinv[row_a + 8] : 0.0f;
    #pragma unroll
    for (int nt = 0; nt < 16; nt++) {
        int col = nt * 8 + tig * 2;
        if (v0) {
            __half2 v = __floats2half2_rn(acc[nt][0] * di0, acc[nt][1] * di0);
            *(__half2*)&g_h0[(size_t)row_a * FDIM + col] = v;
        }
        if (v1) {
            __half2 v = __floats2half2_rn(acc[nt][2] * di1, acc[nt][3] * di1);
            *(__half2*)&g_h0[(size_t)(row_a + 8) * FDIM + col] = v;
        }
    }
}

// ---- K6: pull-mode layer-1 aggregation + fused finalize. ----
__global__ void pull1_k(const float* __restrict__ b1, int n) {
    int wid_g = (blockIdx.x * blockDim.x + threadIdx.x) >> 5;
    int lane = threadIdx.x & 31;
    if (wid_g >= n) return;
    int beg = g_rowstart[wid_g];
    int end = g_rowstart[wid_g + 1];
    const uint2* H0 = (const uint2*)g_h0;

    uint2 sv = H0[(size_t)wid_g * 32 + lane];            // self-loop term
    float2 s0 = __half22float2(*(const __half2*)&sv.x);
    float2 s1 = __half22float2(*(const __half2*)&sv.y);
    float4 acc = make_float4(s0.x, s0.y, s1.x, s1.y);

    for (int j0 = beg; j0 < end; j0 += 32) {
        int id = (j0 + lane < end) ? g_csr[j0 + lane] : 0;   // one coalesced load
        int m = min(32, end - j0);
        for (int jj = 0; jj < m; jj += 8) {
            #pragma unroll
            for (int k = 0; k < 8; k++) {
                int j = jj + k;
                int s = __shfl_sync(0xffffffffu, id, j & 31);
                if (j < m) {
                    uint2 v = H0[(size_t)s * 32 + lane];
                    float2 p0 = __half22float2(*(const __half2*)&v.x);
                    float2 p1 = __half22float2(*(const __half2*)&v.y);
                    acc.x += p0.x; acc.y += p0.y; acc.z += p1.x; acc.w += p1.y;
                }
            }
        }
    }
    float di = g_dinv[wid_g];
    float4 bb = ((const float4*)b1)[lane];
    acc.x = fmaxf(fmaf(acc.x, di, bb.x), 0.0f);
    acc.y = fmaxf(fmaf(acc.y, di, bb.y), 0.0f);
    acc.z = fmaxf(fmaf(acc.z, di, bb.z), 0.0f);
    acc.w = fmaxf(fmaf(acc.w, di, bb.w), 0.0f);
    ((float4*)g_h1)[(size_t)wid_g * 32 + lane] = acc;
}

// ---- K7: g_t2 = (h1 @ W2) * dinv[row], fp16 out ----
__global__ void gemm2_k(const float* __restrict__ W2, int n) {
    __shared__ float ws[FDIM * F2];
    __shared__ float hs[8][FDIM];
    int tid = threadIdx.x;               // 128 threads
    #pragma unroll
    for (int i = 0; i < F2; i++) ws[i * FDIM + tid] = W2[i * FDIM + tid];
    long long r0 = (long long)blockIdx.x * 8;
    #pragma unroll
    for (int j = 0; j < 8; j++) {
        long long r = r0 + j;
        hs[j][tid] = (r < n) ? g_h1[r * FDIM + tid] : 0.0f;
    }
    __syncthreads();
    int lr = tid >> 4;                   // local row 0..7
    int c  = tid & 15;                   // col 0..15
    float acc = 0.0f;
    #pragma unroll 8
    for (int k = 0; k < FDIM; k++) acc = fmaf(hs[lr][k], ws[k * F2 + c], acc);
    long long r = r0 + lr;
    if (r < n) g_t2[r * F2 + c] = __float2half_rn(acc * g_dinv[r]);
}

// ---- K8: pull-mode layer-2 aggregation + fused finalize, writes d_out. ----
__global__ void pull2_k(const float* __restrict__ b2, float* __restrict__ out, int n) {
    int t = blockIdx.x * blockDim.x + threadIdx.x;
    if (t >= n * 4) return;
    int node = t >> 2, q = t & 3;
    int beg = g_rowstart[node];
    int end = g_rowstart[node + 1];
    const uint2* T2 = (const uint2*)g_t2;

    uint2 sv = T2[(size_t)node * 4 + q];                 // self-loop term
    float2 s0 = __half22float2(*(const __half2*)&sv.x);
    float2 s1 = __half22float2(*(const __half2*)&sv.y);
    float4 acc = make_float4(s0.x, s0.y, s1.x, s1.y);

    #pragma unroll 4
    for (int j = beg; j < end; j++) {
        int s = __ldg(&g_csr[j]);
        uint2 v = T2[(size_t)s * 4 + q];
        float2 p0 = __half22float2(*(const __half2*)&v.x);
        float2 p1 = __half22float2(*(const __half2*)&v.y);
        acc.x += p0.x; acc.y += p0.y; acc.z += p1.x; acc.w += p1.y;
    }
    float di = g_dinv[node];
    float4 bb = ((const float4*)b2)[q];
    acc.x = fmaf(acc.x, di, bb.x);
    acc.y = fmaf(acc.y, di, bb.y);
    acc.z = fmaf(acc.z, di, bb.z);
    acc.w = fmaf(acc.w, di, bb.w);
    ((float4*)out)[(size_t)node * 4 + q] = acc;
}

extern "C" void kernel_launch(void* const* d_in, const int* in_sizes, int n_in,
                              void* d_out, int out_size) {
    const float* x  = (const float*)d_in[0];
    const void*  ei = d_in[1];
    const float* W1 = (const float*)d_in[2];
    const float* b1 = (const float*)d_in[3];
    const float* W2 = (const float*)d_in[4];
    const float* b2 = (const float*)d_in[5];
    float* out = (float*)d_out;

    int n = in_sizes[0] / FDIM;   // 100000
    int e = in_sizes[1] / 2;      // 1600000

    const int ws_bytes = 64 * WP_STRIDE * sizeof(unsigned);  // 34816
    cudaFuncSetAttribute(gemm1_k, cudaFuncAttributeMaxDynamicSharedMemorySize, ws_bytes);

    int nblk = (n + SCAN_TPB - 1) / SCAN_TPB;

    zero_probe_k<<<(n + 255) / 256, 256>>>((const unsigned long long*)ei, n);  // 1
    hist_k<<<(e + 255) / 256, 256>>>(ei, e);                                   // 2
    scan_phase1_k<<<nblk, SCAN_TPB>>>(n);                                      // 3 (also dinv)
    gemm1_k<<<(n + 127) / 128, 256, ws_bytes>>>(x, W1, n);                     // 4 <- ncu capture
    scan_phase3_k<<<nblk, SCAN_TPB>>>(n);                                      // 5
    fill_k<<<(e + 255) / 256, 256>>>(ei, e);                                   // 6

    long long w1t = (long long)n * 32;   // one warp per node
    pull1_k<<<(unsigned)((w1t + 255) / 256), 256>>>(b1, n);                    // 7

    gemm2_k<<<(n + 7) / 8, 128>>>(W2, n);                                      // 8

    long long p2t = (long long)n * 4;    // 4 threads per node
    pull2_k<<<(unsigned)((p2t + 255) / 256), 256>>>(b2, out, n);               // 9
}